// round 15
// baseline (speedup 1.0000x reference)
#include <cuda_runtime.h>
#include <cuda_bf16.h>
#include <cstdint>
#include <math.h>

#define N_ENT 50000
#define R_REL 400
#define D 300
#define NT 50400
#define E_EDGES 800000
#define B 2048
#define L 32
#define H 8
#define DK 32
#define HD 256
#define G1 0.9f
#define G2 0.2f
#define KPAD 320
#define KP6 608

// ---------------- device scratch ----------------
__device__ __align__(16) float g_x[NT * D];
__device__ __align__(16) float g_y[NT * D];
__device__ __align__(16) float g_ekv[(size_t)NT * 1024];       // [row][dir*512 + (K | V)]
__device__ __align__(16) float g_q[(size_t)2 * B * 512];       // [b2][dir*256 + hd]
__device__ __align__(16) float g_wcomb[2 * HD * D];            // Wo@Wp per dir, fp32
__device__ __align__(16) __nv_bfloat16 g_ahi[(size_t)NT * KPAD];
__device__ __align__(16) __nv_bfloat16 g_alo[(size_t)NT * KPAD];
__device__ __align__(16) __nv_bfloat16 g_w1hi[300 * KPAD];
__device__ __align__(16) __nv_bfloat16 g_w1lo[300 * KPAD];
__device__ __align__(16) __nv_bfloat16 g_w2hi[300 * KPAD];
__device__ __align__(16) __nv_bfloat16 g_w2lo[300 * KPAD];
__device__ __align__(16) __nv_bfloat16 g_wkvhi[1024 * KPAD];
__device__ __align__(16) __nv_bfloat16 g_wkvlo[1024 * KPAD];
__device__ __align__(16) __nv_bfloat16 g_wqhi[512 * KPAD];
__device__ __align__(16) __nv_bfloat16 g_wqlo[512 * KPAD];
__device__ __align__(16) __nv_bfloat16 g_wchi[300 * 512];      // Wcomb^T split (both dirs)
__device__ __align__(16) __nv_bfloat16 g_wclo[300 * 512];
__device__ __align__(16) __nv_bfloat16 g_khi[2 * B * KPAD];
__device__ __align__(16) __nv_bfloat16 g_klo[2 * B * KPAD];
__device__ __align__(16) __nv_bfloat16 g_chi[(size_t)2 * B * 512];  // masked ctx [b2][dir*256+hd]
__device__ __align__(16) __nv_bfloat16 g_clo[(size_t)2 * B * 512];
__device__ __align__(16) __nv_bfloat16 g_n1hi[B * KP6];
__device__ __align__(16) __nv_bfloat16 g_n1lo[B * KP6];
__device__ __align__(16) __nv_bfloat16 g_n2hi[B * KP6];
__device__ __align__(16) __nv_bfloat16 g_n2lo[B * KP6];
__device__ int   g_cnt[NT];
__device__ int   g_cursor[NT];
__device__ int   g_rowptr[NT + 1];
__device__ int   g_bsum[256];
__device__ int   g_csr_src[E_EDGES];
__device__ float g_csr_w[E_EDGES];
__device__ float g_acc[2];
__device__ int   g_maskmode;

// ---------------- PTX helpers ----------------
__device__ __forceinline__ uint32_t smem_u32(const void* p) {
    uint32_t a;
    asm("{ .reg .u64 t; cvta.to.shared.u64 t, %1; cvt.u32.u64 %0, t; }" : "=r"(a) : "l"(p));
    return a;
}
__device__ __forceinline__ void cpa16(uint32_t s, const void* g) {
    asm volatile("cp.async.cg.shared.global [%0], [%1], 16;" :: "r"(s), "l"(g));
}
__device__ __forceinline__ void cpa_commit() { asm volatile("cp.async.commit_group;" ::); }
template <int NN> __device__ __forceinline__ void cpa_wait() {
    asm volatile("cp.async.wait_group %0;" :: "n"(NN));
}
__device__ __forceinline__ void ldm4(uint32_t* r, uint32_t a) {
    asm volatile("ldmatrix.sync.aligned.m8n8.x4.shared.b16 {%0,%1,%2,%3}, [%4];"
        : "=r"(r[0]), "=r"(r[1]), "=r"(r[2]), "=r"(r[3]) : "r"(a));
}
__device__ __forceinline__ void mma16816(float* c, const uint32_t* a, const uint32_t* b) {
    asm volatile("mma.sync.aligned.m16n8k16.row.col.f32.bf16.bf16.f32 "
        "{%0,%1,%2,%3}, {%4,%5,%6,%7}, {%8,%9}, {%0,%1,%2,%3};"
        : "+f"(c[0]), "+f"(c[1]), "+f"(c[2]), "+f"(c[3])
        : "r"(a[0]), "r"(a[1]), "r"(a[2]), "r"(a[3]), "r"(b[0]), "r"(b[1]));
}

// ---------------- mask dtype autodetect ----------------
__device__ __forceinline__ int read_mask(const void* p, int i) {
    if (g_maskmode) return ((const unsigned char*)p)[i] != 0;
    return ((const int*)p)[i] != 0;
}
__global__ void detect_mask_kernel(const unsigned char* __restrict__ m) {
    __shared__ int found;
    if (threadIdx.x == 0) found = 0;
    __syncthreads();
    for (int i = threadIdx.x; i < 4096; i += 256)
        if ((i & 3) && m[i]) found = 1;
    __syncthreads();
    if (threadIdx.x == 0) g_maskmode = found;
}

// ---------------- conversions ----------------
__global__ void conv_split(const float* __restrict__ src, int rows, int scols, int kpad,
                           __nv_bfloat16* __restrict__ hi, __nv_bfloat16* __restrict__ lo) {
    int idx = blockIdx.x * blockDim.x + threadIdx.x;
    if (idx >= rows * kpad) return;
    int r = idx / kpad, c = idx - r * kpad;
    float v = (c < scols) ? src[(size_t)r * scols + c] : 0.f;
    __nv_bfloat16 h = __float2bfloat16(v);
    hi[idx] = h;
    lo[idx] = __float2bfloat16(v - __bfloat162float(h));
}
__global__ void conv_split4(const float* __restrict__ src, int rows, int scols, int kpad,
                            __nv_bfloat16* __restrict__ hi, __nv_bfloat16* __restrict__ lo) {
    int idx = blockIdx.x * blockDim.x + threadIdx.x;
    int kq = kpad >> 2;
    if (idx >= rows * kq) return;
    int r = idx / kq, c4 = (idx - r * kq) << 2;
    float4 v = make_float4(0.f, 0.f, 0.f, 0.f);
    if (c4 + 4 <= scols)
        v = *reinterpret_cast<const float4*>(src + (size_t)r * scols + c4);
    __nv_bfloat16 h[4], l[4];
    float vf[4] = {v.x, v.y, v.z, v.w};
#pragma unroll
    for (int j = 0; j < 4; j++) {
        h[j] = __float2bfloat16(vf[j]);
        l[j] = __float2bfloat16(vf[j] - __bfloat162float(h[j]));
    }
    size_t off = (size_t)r * kpad + c4;
    *reinterpret_cast<uint2*>(hi + off) = *reinterpret_cast<uint2*>(h);
    *reinterpret_cast<uint2*>(lo + off) = *reinterpret_cast<uint2*>(l);
}
__global__ void conv_splitT(const float* __restrict__ W, int K, int Nn, int kpad,
                            __nv_bfloat16* __restrict__ hi, __nv_bfloat16* __restrict__ lo) {
    int idx = blockIdx.x * blockDim.x + threadIdx.x;
    if (idx >= Nn * kpad) return;
    int n = idx / kpad, k = idx - n * kpad;
    float v = (k < K) ? W[(size_t)k * Nn + n] : 0.f;
    __nv_bfloat16 h = __float2bfloat16(v);
    hi[idx] = h;
    lo[idx] = __float2bfloat16(v - __bfloat162float(h));
}
// writes only k in [0,K) at column offset koff (no padding writes)
__global__ void conv_splitT_off(const float* __restrict__ W, int K, int Nn, int kpad, int koff,
                                __nv_bfloat16* __restrict__ hi, __nv_bfloat16* __restrict__ lo) {
    int idx = blockIdx.x * blockDim.x + threadIdx.x;
    if (idx >= Nn * K) return;
    int n = idx / K, k = idx - n * K;
    float v = W[(size_t)k * Nn + n];
    __nv_bfloat16 h = __float2bfloat16(v);
    size_t o = (size_t)n * kpad + koff + k;
    hi[o] = h;
    lo[o] = __float2bfloat16(v - __bfloat162float(h));
}
__global__ void conv_splitT_kv(const float* __restrict__ Wk, const float* __restrict__ Wv,
                               __nv_bfloat16* __restrict__ hi, __nv_bfloat16* __restrict__ lo) {
    int idx = blockIdx.x * blockDim.x + threadIdx.x;
    if (idx >= 512 * KPAD) return;
    int n = idx / KPAD, k = idx - n * KPAD;
    float v = 0.f;
    if (k < D) v = (n < HD) ? Wk[(size_t)k * HD + n] : Wv[(size_t)k * HD + (n - HD)];
    __nv_bfloat16 h = __float2bfloat16(v);
    hi[idx] = h;
    lo[idx] = __float2bfloat16(v - __bfloat162float(h));
}

// =====================================================================
// bf16x3 warp-MMA GEMM core
// =====================================================================
__device__ __forceinline__ void mma_core(
    const __nv_bfloat16* __restrict__ Ahi, const __nv_bfloat16* __restrict__ Alo,
    const __nv_bfloat16* __restrict__ Bhi, const __nv_bfloat16* __restrict__ Blo,
    int M, int Ntot, int kpad, int m0, int n0g,
    uint32_t sbase, float acc[2][8][4])
{
    const int tid = threadIdx.x;
    const int lane = tid & 31;
    const int wid = tid >> 5;
    const int wm = (wid & 3) * 32;
    const int wn = (wid >> 2) * 64;
    const int NS2 = kpad >> 5;

    auto load_stage = [&](int slot, int ks) {
        int kb = ks << 5;
        uint32_t st = sbase + (uint32_t)slot * 32768u;
#pragma unroll
        for (int rep = 0; rep < 8; rep++) {
            int i = tid + rep * 256;
            int region = i >> 10;
            int il = i & 1023;
            int v = il >> 9, r = (il >> 2) & 127, c = il & 3;
            int pc = c ^ ((r >> 1) & 3);
            const __nv_bfloat16* src;
            if (region == 0) {
                int gr = m0 + r; if (gr >= M) gr = M - 1;
                src = (v ? Alo : Ahi) + (size_t)gr * kpad + kb + c * 8;
            } else {
                int gr = n0g + r; if (gr >= Ntot) gr = Ntot - 1;
                src = (v ? Blo : Bhi) + (size_t)gr * kpad + kb + c * 8;
            }
            cpa16(st + (uint32_t)region * 16384u + (uint32_t)v * 8192u
                  + (uint32_t)r * 64u + (uint32_t)pc * 16u, src);
        }
        cpa_commit();
    };

    load_stage(0, 0);
    load_stage(1, 1);

    const int a_r = wm + ((lane >> 3) & 1) * 8 + (lane & 7);
    const int a_c = lane >> 4;
    const int b_r = wn + ((lane >> 4) & 1) * 8 + (lane & 7);
    const int b_c = (lane >> 3) & 1;

    for (int i = 0; i < NS2; i++) {
        if (i + 1 < NS2) cpa_wait<1>(); else cpa_wait<0>();
        __syncthreads();
        if (i + 2 < NS2) load_stage((i + 2) % 3, i + 2);
        uint32_t st = sbase + (uint32_t)(i % 3) * 32768u;
#pragma unroll
        for (int hh = 0; hh < 2; hh++) {
            int cb = hh * 2;
            uint32_t af[2][2][4];
#pragma unroll
            for (int v = 0; v < 2; v++)
#pragma unroll
                for (int t = 0; t < 2; t++) {
                    int r2 = a_r + t * 16;
                    int pc = (cb + a_c) ^ ((r2 >> 1) & 3);
                    ldm4(af[v][t], st + (uint32_t)v * 8192u + (uint32_t)r2 * 64u
                                   + (uint32_t)pc * 16u);
                }
            uint32_t bf[2][8][2];
#pragma unroll
            for (int v = 0; v < 2; v++)
#pragma unroll
                for (int p = 0; p < 4; p++) {
                    int r2 = b_r + p * 16;
                    int pc = (cb + b_c) ^ ((r2 >> 1) & 3);
                    uint32_t tmp[4];
                    ldm4(tmp, st + 16384u + (uint32_t)v * 8192u + (uint32_t)r2 * 64u
                              + (uint32_t)pc * 16u);
                    bf[v][p * 2][0] = tmp[0]; bf[v][p * 2][1] = tmp[1];
                    bf[v][p * 2 + 1][0] = tmp[2]; bf[v][p * 2 + 1][1] = tmp[3];
                }
#pragma unroll
            for (int t = 0; t < 2; t++)
#pragma unroll
                for (int nt = 0; nt < 8; nt++) {
                    mma16816(acc[t][nt], af[0][t], bf[0][nt]);
                    mma16816(acc[t][nt], af[0][t], bf[1][nt]);
                    mma16816(acc[t][nt], af[1][t], bf[0][nt]);
                }
        }
    }
}

__global__ __launch_bounds__(256) void mma_gemm(
    const __nv_bfloat16* __restrict__ Ahi, const __nv_bfloat16* __restrict__ Alo,
    const __nv_bfloat16* __restrict__ Bhi, const __nv_bfloat16* __restrict__ Blo,
    float* __restrict__ C, __nv_bfloat16* __restrict__ Chi, __nv_bfloat16* __restrict__ Clo,
    int M, int Ntot, int ldc, int kpad,
    const float* __restrict__ bias)
{
    extern __shared__ char dsm[];
    const int lane = threadIdx.x & 31;
    const int wid = threadIdx.x >> 5;
    const int wm = (wid & 3) * 32, wn = (wid >> 2) * 64;
    const int m0 = blockIdx.y * 128, n0g = blockIdx.x * 128;
    float acc[2][8][4];
#pragma unroll
    for (int t = 0; t < 2; t++)
#pragma unroll
        for (int nt = 0; nt < 8; nt++)
#pragma unroll
            for (int j = 0; j < 4; j++) acc[t][nt][j] = 0.f;

    mma_core(Ahi, Alo, Bhi, Blo, M, Ntot, kpad, m0, n0g, smem_u32(dsm), acc);

#pragma unroll
    for (int t = 0; t < 2; t++) {
        int gm0 = m0 + wm + t * 16 + (lane >> 2);
#pragma unroll
        for (int nt = 0; nt < 8; nt++) {
            int gn = n0g + wn + nt * 8 + ((lane & 3) << 1);
            if (gn >= Ntot) continue;
#pragma unroll
            for (int half = 0; half < 2; half++) {
                int gm = gm0 + half * 8;
                if (gm >= M) continue;
                float c0 = acc[t][nt][half * 2 + 0];
                float c1 = acc[t][nt][half * 2 + 1];
                if (bias) { c0 += bias[gn]; c1 += bias[gn + 1]; }
                size_t orow = (size_t)gm * ldc;
                if (Chi) {
                    __nv_bfloat16 h0 = __float2bfloat16(c0);
                    Chi[orow + gn] = h0;
                    Clo[orow + gn] = __float2bfloat16(c0 - __bfloat162float(h0));
                    if (gn + 1 < Ntot) {
                        __nv_bfloat16 h1 = __float2bfloat16(c1);
                        Chi[orow + gn + 1] = h1;
                        Clo[orow + gn + 1] = __float2bfloat16(c1 - __bfloat162float(h1));
                    }
                } else {
                    C[orow + gn] = c0;
                    if (gn + 1 < Ntot) C[orow + gn + 1] = c1;
                }
            }
        }
    }
}

// sim = n1 * n2^T with in-register loss reduction
__global__ __launch_bounds__(256) void mma_sim(
    const __nv_bfloat16* __restrict__ Ahi, const __nv_bfloat16* __restrict__ Alo,
    const __nv_bfloat16* __restrict__ Bhi, const __nv_bfloat16* __restrict__ Blo)
{
    extern __shared__ char dsm[];
    const int tid = threadIdx.x;
    const int lane = tid & 31;
    const int wid = tid >> 5;
    const int wm = (wid & 3) * 32, wn = (wid >> 2) * 64;
    const int m0 = blockIdx.y * 128, n0g = blockIdx.x * 128;
    float acc[2][8][4];
#pragma unroll
    for (int t = 0; t < 2; t++)
#pragma unroll
        for (int nt = 0; nt < 8; nt++)
#pragma unroll
            for (int j = 0; j < 4; j++) acc[t][nt][j] = 0.f;

    mma_core(Ahi, Alo, Bhi, Blo, B, B, KP6, m0, n0g, smem_u32(dsm), acc);

    float neg = 0.f, dia = 0.f;
#pragma unroll
    for (int t = 0; t < 2; t++) {
        int gm0 = m0 + wm + t * 16 + (lane >> 2);
#pragma unroll
        for (int nt = 0; nt < 8; nt++) {
            int gn = n0g + wn + nt * 8 + ((lane & 3) << 1);
#pragma unroll
            for (int half = 0; half < 2; half++) {
                int gm = gm0 + half * 8;
#pragma unroll
                for (int j = 0; j < 2; j++) {
                    float c = acc[t][nt][half * 2 + j];
                    if (gm == gn + j) dia += fminf(c, G1);
                    else neg += fmaxf(c, G2);
                }
            }
        }
    }
    __syncthreads();
    float* red = (float*)dsm;
    red[tid] = neg; __syncthreads();
    for (int s2 = 128; s2; s2 >>= 1) { if (tid < s2) red[tid] += red[tid + s2]; __syncthreads(); }
    if (tid == 0) atomicAdd(&g_acc[0], red[0]);
    __syncthreads();
    red[tid] = dia; __syncthreads();
    for (int s2 = 128; s2; s2 >>= 1) { if (tid < s2) red[tid] += red[tid + s2]; __syncthreads(); }
    if (tid == 0) atomicAdd(&g_acc[1], red[0]);
}

// ---------------- SIMT SGEMM (tiny Wrel + Wcomb GEMMs) ----------------
__global__ __launch_bounds__(256) void sgemm_rr(
    const float* __restrict__ A, int lda, const float* __restrict__ Bm, int ldb,
    float* __restrict__ C, int ldc, int M, int Nn, int K,
    const float* __restrict__ bias)
{
    __shared__ float As[8][128];
    __shared__ float Bs[8][128];
    const int tid = threadIdx.x;
    const int m0 = blockIdx.y * 128, n0 = blockIdx.x * 128;
    const int arow = tid >> 1, acol = (tid & 1) << 2;
    const int brow = tid >> 5, bcol = (tid & 31) << 2;
    const int ty = tid >> 4, tx = tid & 15;
    const int tm = ty << 3, tn = tx << 3;
    float acc[8][8];
#pragma unroll
    for (int i = 0; i < 8; i++)
#pragma unroll
        for (int j = 0; j < 8; j++) acc[i][j] = 0.f;
    for (int k0 = 0; k0 < K; k0 += 8) {
        float4 av = make_float4(0.f, 0.f, 0.f, 0.f);
        { int gm = m0 + arow, gk = k0 + acol;
          if (gm < M && gk < K) av = *reinterpret_cast<const float4*>(A + (size_t)gm * lda + gk); }
        As[acol + 0][arow] = av.x; As[acol + 1][arow] = av.y;
        As[acol + 2][arow] = av.z; As[acol + 3][arow] = av.w;
        float4 bv = make_float4(0.f, 0.f, 0.f, 0.f);
        { int gk = k0 + brow, gn = n0 + bcol;
          if (gk < K && gn < Nn) bv = *reinterpret_cast<const float4*>(Bm + (size_t)gk * ldb + gn); }
        *reinterpret_cast<float4*>(&Bs[brow][bcol]) = bv;
        __syncthreads();
#pragma unroll
        for (int kk = 0; kk < 8; kk++) {
            float4 a0 = *reinterpret_cast<const float4*>(&As[kk][tm]);
            float4 a1 = *reinterpret_cast<const float4*>(&As[kk][tm + 4]);
            float4 b0 = *reinterpret_cast<const float4*>(&Bs[kk][tn]);
            float4 b1 = *reinterpret_cast<const float4*>(&Bs[kk][tn + 4]);
            float af[8] = {a0.x, a0.y, a0.z, a0.w, a1.x, a1.y, a1.z, a1.w};
            float bf[8] = {b0.x, b0.y, b0.z, b0.w, b1.x, b1.y, b1.z, b1.w};
#pragma unroll
            for (int i = 0; i < 8; i++)
#pragma unroll
                for (int j = 0; j < 8; j++) acc[i][j] = fmaf(af[i], bf[j], acc[i][j]);
        }
        __syncthreads();
    }
#pragma unroll
    for (int i = 0; i < 8; i++) {
        int gm = m0 + tm + i;
        if (gm >= M) continue;
#pragma unroll
        for (int j = 0; j < 8; j++) {
            int gn = n0 + tn + j;
            if (gn >= Nn) continue;
            float c = acc[i][j];
            if (bias) c += bias[gn];
            C[(size_t)gm * ldc + gn] = c;
        }
    }
}

// ---------------- CSR build ----------------
__global__ void hist_kernel(const int* __restrict__ dst) {
    int e = blockIdx.x * blockDim.x + threadIdx.x;
    if (e < E_EDGES) atomicAdd(&g_cnt[dst[e]], 1);
}
__global__ void scan1_kernel() {
    __shared__ int sh[256];
    int i = blockIdx.x * 256 + threadIdx.x;
    sh[threadIdx.x] = (i < NT) ? g_cnt[i] : 0;
    __syncthreads();
    for (int o = 128; o; o >>= 1) { if (threadIdx.x < o) sh[threadIdx.x] += sh[threadIdx.x + o]; __syncthreads(); }
    if (!threadIdx.x) g_bsum[blockIdx.x] = sh[0];
}
__global__ void scan2_kernel(int nb) {
    __shared__ int sh[256];
    int t = threadIdx.x;
    int v = (t < nb) ? g_bsum[t] : 0;
    sh[t] = v; __syncthreads();
    for (int o = 1; o < 256; o <<= 1) {
        int u = (t >= o) ? sh[t - o] : 0; __syncthreads();
        sh[t] += u; __syncthreads();
    }
    g_bsum[t] = sh[t] - v;
}
__global__ void scan3_kernel() {
    __shared__ int sh[256];
    int t = threadIdx.x, i = blockIdx.x * 256 + t;
    int v = (i < NT) ? g_cnt[i] : 0;
    sh[t] = v; __syncthreads();
    for (int o = 1; o < 256; o <<= 1) {
        int u = (t >= o) ? sh[t - o] : 0; __syncthreads();
        sh[t] += u; __syncthreads();
    }
    int off = g_bsum[blockIdx.x] + sh[t] - v;
    if (i < NT) {
        g_rowptr[i] = off; g_cursor[i] = off;
        if (i == NT - 1) g_rowptr[NT] = off + v;
    }
}
__global__ void scatter_kernel(const int* __restrict__ src, const int* __restrict__ dst,
                               const float* __restrict__ w) {
    int e = blockIdx.x * blockDim.x + threadIdx.x;
    if (e < E_EDGES) {
        int d = dst[e];
        int p = atomicAdd(&g_cursor[d], 1);
        g_csr_src[p] = src[e];
        g_csr_w[p] = w[e];
    }
}

// ---------------- segment sum (float4, fused bias/relu + dual output) ----
__global__ void segsum_kernel(const float* __restrict__ Y, float* __restrict__ O,
                              __nv_bfloat16* __restrict__ Ohi, __nv_bfloat16* __restrict__ Olo,
                              const float* __restrict__ bias, int doRelu) {
    int gw = (blockIdx.x * blockDim.x + threadIdx.x) >> 5;
    int lane = threadIdx.x & 31;
    if (gw >= NT) return;
    int beg = g_rowptr[gw], end = g_rowptr[gw + 1];
    float4 acc[3];
#pragma unroll
    for (int j = 0; j < 3; j++) acc[j] = make_float4(0.f, 0.f, 0.f, 0.f);
    const int v2 = (lane < 11);
    for (int e = beg; e < end; e++) {
        int sI = g_csr_src[e];
        float w = g_csr_w[e];
        const float4* yr = reinterpret_cast<const float4*>(Y + (size_t)sI * D);
#pragma unroll
        for (int j = 0; j < 3; j++) {
            if (j < 2 || v2) {
                float4 v = yr[lane + (j << 5)];
                acc[j].x = fmaf(w, v.x, acc[j].x);
                acc[j].y = fmaf(w, v.y, acc[j].y);
                acc[j].z = fmaf(w, v.z, acc[j].z);
                acc[j].w = fmaf(w, v.w, acc[j].w);
            }
        }
    }
    const float4* b4 = reinterpret_cast<const float4*>(bias);
#pragma unroll
    for (int j = 0; j < 3; j++) {
        if (j == 2 && !v2) continue;
        int c4 = lane + (j << 5);
        float4 bb = b4[c4];
        float4 v = acc[j];
        v.x += bb.x; v.y += bb.y; v.z += bb.z; v.w += bb.w;
        if (doRelu) {
            v.x = fmaxf(v.x, 0.f); v.y = fmaxf(v.y, 0.f);
            v.z = fmaxf(v.z, 0.f); v.w = fmaxf(v.w, 0.f);
        }
        if (O) reinterpret_cast<float4*>(O + (size_t)gw * D)[c4] = v;
        if (Ohi) {
            __nv_bfloat16 h[4], l[4];
            float vf[4] = {v.x, v.y, v.z, v.w};
#pragma unroll
            for (int q = 0; q < 4; q++) {
                h[q] = __float2bfloat16(vf[q]);
                l[q] = __float2bfloat16(vf[q] - __bfloat162float(h[q]));
            }
            size_t off = (size_t)gw * KPAD + c4 * 4;
            *reinterpret_cast<uint2*>(Ohi + off) = *reinterpret_cast<uint2*>(h);
            *reinterpret_cast<uint2*>(Olo + off) = *reinterpret_cast<uint2*>(l);
        }
    }
}

// ---------------- encoder pieces ----------------
__global__ void gather_ker2_kernel(const int* __restrict__ ids_l, const int* __restrict__ ids_r,
                                   float* __restrict__ outbase) {
    int b2 = blockIdx.x, c = threadIdx.x;
    if (c >= D) return;
    int side = (b2 >= B);
    int b = b2 - side * B;
    const int* ids = side ? ids_r : ids_l;
    float v = g_x[(size_t)ids[b] * D + c];
    outbase[(size_t)b2 * (2 * D) + c] = v;
    __nv_bfloat16 h = __float2bfloat16(v);
    g_khi[(size_t)b2 * KPAD + c] = h;
    g_klo[(size_t)b2 * KPAD + c] = __float2bfloat16(v - __bfloat162float(h));
}

// attention for ONE dir (both sides); writes MASK-SCALED ctx into [b2][dir*256+hd]
__global__ __launch_bounds__(256) void attn_dir(
    int dir,
    const int* __restrict__ hL, const int* __restrict__ rL, const void* __restrict__ mL,
    const int* __restrict__ hR, const int* __restrict__ rR, const void* __restrict__ mR)
{
    __shared__ float T[8][32][33];
    int wid = threadIdx.x >> 5, lane = threadIdx.x & 31;
    int gw = blockIdx.x * 8 + wid;
    int h = gw & 7;
    int b2 = gw >> 3;                 // [0, 2B)
    int side = b2 >> 11;
    int b = b2 & 2047;
    const int* head = side ? hR : hL;
    const int* rel  = side ? rR : rL;
    const void* mask = side ? mR : mL;
    int h32 = h * 32;
    int kcol = dir * 512 + h32;
    int t_l = head[b * L + lane];
    int r_l = N_ENT + rel[b * L + lane];
    float (*Tl)[33] = T[wid];
#pragma unroll 4
    for (int l = 0; l < 32; l++) {
        int t = __shfl_sync(0xffffffffu, t_l, l);
        int r = __shfl_sync(0xffffffffu, r_l, l);
        Tl[l][lane] = g_ekv[(size_t)t * 1024 + kcol + lane]
                    + g_ekv[(size_t)r * 1024 + kcol + lane];
    }
    float qv = g_q[(size_t)b2 * 512 + dir * 256 + h32 + lane];
    __syncwarp();
    float s = 0.f;
#pragma unroll
    for (int d = 0; d < 32; d++)
        s = fmaf(__shfl_sync(0xffffffffu, qv, d), Tl[lane][d], s);
    int mk = read_mask(mask, b * L + lane);
    unsigned bal = __ballot_sync(0xffffffffu, mk);
    s = mk ? s * 0.17677669529663687f : -1e9f;
    float mx = s;
#pragma unroll
    for (int o = 16; o; o >>= 1) mx = fmaxf(mx, __shfl_xor_sync(0xffffffffu, mx, o));
    float e = expf(s - mx);
    float sum = e;
#pragma unroll
    for (int o = 16; o; o >>= 1) sum += __shfl_xor_sync(0xffffffffu, sum, o);
    float at = e / sum;
    float c = 0.f;
#pragma unroll 4
    for (int l = 0; l < 32; l++) {
        int t = __shfl_sync(0xffffffffu, t_l, l);
        int r = __shfl_sync(0xffffffffu, r_l, l);
        float v = g_ekv[(size_t)t * 1024 + kcol + 256 + lane]
                + g_ekv[(size_t)r * 1024 + kcol + 256 + lane];
        c = fmaf(__shfl_sync(0xffffffffu, at, l), v, c);
    }
    if (bal == 0u) c = 0.f;           // mask.any row-zero folded into ctx
    __nv_bfloat16 hc = __float2bfloat16(c);
    size_t oidx = (size_t)b2 * 512 + dir * 256 + h32 + lane;
    g_chi[oidx] = hc;
    g_clo[oidx] = __float2bfloat16(c - __bfloat162float(hc));
}

// ---------------- cosine norm over 2B rows ----------------
__global__ void norm2_kernel(const float* __restrict__ srcbase) {
    int w2 = (blockIdx.x * blockDim.x + threadIdx.x) >> 5;
    int lane = threadIdx.x & 31;
    if (w2 >= 2 * B) return;
    const float* s = srcbase + (size_t)w2 * (2 * D);
    float ss = 0.f;
    for (int c = lane; c < 2 * D; c += 32) { float v = s[c]; ss = fmaf(v, v, ss); }
#pragma unroll
    for (int o = 16; o; o >>= 1) ss += __shfl_xor_sync(0xffffffffu, ss, o);
    float sc = 1.f / fmaxf(sqrtf(ss), 1e-8f);
    int side = (w2 >= B);
    int w = w2 - side * B;
    __nv_bfloat16* dhi = side ? g_n2hi : g_n1hi;
    __nv_bfloat16* dlo = side ? g_n2lo : g_n1lo;
    for (int c = lane; c < 2 * D; c += 32) {
        float v = s[c] * sc;
        __nv_bfloat16 h = __float2bfloat16(v);
        dhi[(size_t)w * KP6 + c] = h;
        dlo[(size_t)w * KP6 + c] = __float2bfloat16(v - __bfloat162float(h));
    }
}
__global__ void finalize_kernel(float* __restrict__ out) {
    float neg_sum = g_acc[0] + (float)B * fmaxf(0.f, G2);
    float neg_part = neg_sum / (float)((size_t)B * B);
    float pos_part = g_acc[1] / (float)B;
    out[0] = neg_part - G2 - pos_part + G1;
}

// =====================================================================
extern "C" void kernel_launch(void* const* d_in, const int* in_sizes, int n_in,
                              void* d_out, int out_size) {
    const float* e_x    = (const float*)d_in[0];
    const float* r_x    = (const float*)d_in[1];
    const float* edge_w = (const float*)d_in[2];
    const float* Wrel   = (const float*)d_in[3];
    const float* brel   = (const float*)d_in[4];
    const float* W1     = (const float*)d_in[5];
    const float* b1     = (const float*)d_in[6];
    const float* W2     = (const float*)d_in[7];
    const float* b2     = (const float*)d_in[8];
    const float* Wprox  = (const float*)d_in[9];
    const float* bprox  = (const float*)d_in[10];
    const float* Wq     = (const float*)d_in[11];
    const float* Wk     = (const float*)d_in[12];
    const float* Wv     = (const float*)d_in[13];
    const float* Wo     = (const float*)d_in[14];
    const int* edge_src = (const int*)d_in[15];
    const int* edge_dst = (const int*)d_in[16];
    float* out = (float*)d_out;

    float *px, *py, *pekv, *pq, *pacc, *pwcomb;
    __nv_bfloat16 *pahi, *palo;
    __nv_bfloat16 *pw1hi, *pw1lo, *pw2hi, *pw2lo, *pwkvhi, *pwkvlo;
    __nv_bfloat16 *pwqhi, *pwqlo, *pwchi, *pwclo;
    __nv_bfloat16 *pkhi, *pklo, *pchi, *pclo;
    __nv_bfloat16 *pn1hi, *pn1lo, *pn2hi, *pn2lo;
    int *pcnt;
    cudaGetSymbolAddress((void**)&px, g_x);
    cudaGetSymbolAddress((void**)&py, g_y);
    cudaGetSymbolAddress((void**)&pekv, g_ekv);
    cudaGetSymbolAddress((void**)&pq, g_q);
    cudaGetSymbolAddress((void**)&pacc, g_acc);
    cudaGetSymbolAddress((void**)&pwcomb, g_wcomb);
    cudaGetSymbolAddress((void**)&pcnt, g_cnt);
    cudaGetSymbolAddress((void**)&pahi, g_ahi);
    cudaGetSymbolAddress((void**)&palo, g_alo);
    cudaGetSymbolAddress((void**)&pw1hi, g_w1hi);
    cudaGetSymbolAddress((void**)&pw1lo, g_w1lo);
    cudaGetSymbolAddress((void**)&pw2hi, g_w2hi);
    cudaGetSymbolAddress((void**)&pw2lo, g_w2lo);
    cudaGetSymbolAddress((void**)&pwkvhi, g_wkvhi);
    cudaGetSymbolAddress((void**)&pwkvlo, g_wkvlo);
    cudaGetSymbolAddress((void**)&pwqhi, g_wqhi);
    cudaGetSymbolAddress((void**)&pwqlo, g_wqlo);
    cudaGetSymbolAddress((void**)&pwchi, g_wchi);
    cudaGetSymbolAddress((void**)&pwclo, g_wclo);
    cudaGetSymbolAddress((void**)&pkhi, g_khi);
    cudaGetSymbolAddress((void**)&pklo, g_klo);
    cudaGetSymbolAddress((void**)&pchi, g_chi);
    cudaGetSymbolAddress((void**)&pclo, g_clo);
    cudaGetSymbolAddress((void**)&pn1hi, g_n1hi);
    cudaGetSymbolAddress((void**)&pn1lo, g_n1lo);
    cudaGetSymbolAddress((void**)&pn2hi, g_n2hi);
    cudaGetSymbolAddress((void**)&pn2lo, g_n2lo);

    cudaFuncSetAttribute(mma_gemm, cudaFuncAttributeMaxDynamicSharedMemorySize, 98304);
    cudaFuncSetAttribute(mma_sim, cudaFuncAttributeMaxDynamicSharedMemorySize, 98304);
    const int SMEM = 98304;
    const int NBLK = (NT + 255) / 256;
    const int MGRID = (NT + 127) / 128;

    static cudaStream_t s1 = nullptr;
    static cudaEvent_t evFork, evRel, evCSR, evW, evH2, evE0, evE1, evAttn;
    if (!s1) {
        cudaStreamCreateWithFlags(&s1, cudaStreamNonBlocking);
        cudaEventCreateWithFlags(&evFork, cudaEventDisableTiming);
        cudaEventCreateWithFlags(&evRel,  cudaEventDisableTiming);
        cudaEventCreateWithFlags(&evCSR,  cudaEventDisableTiming);
        cudaEventCreateWithFlags(&evW,    cudaEventDisableTiming);
        cudaEventCreateWithFlags(&evH2,   cudaEventDisableTiming);
        cudaEventCreateWithFlags(&evE0,   cudaEventDisableTiming);
        cudaEventCreateWithFlags(&evE1,   cudaEventDisableTiming);
        cudaEventCreateWithFlags(&evAttn, cudaEventDisableTiming);
    }
    cudaStream_t s0 = 0;

    cudaEventRecord(evFork, s0);
    cudaStreamWaitEvent(s1, evFork, 0);

    // ===== s1: rel rows, CSR, mask detect, weight conversions, Wcomb =====
    sgemm_rr<<<dim3(3, 4), 256, 0, s1>>>(r_x, 2 * D, Wrel, D, py, D, R_REL, D, 2 * D, brel);
    conv_split<<<(R_REL * KPAD + 255) / 256, 256, 0, s1>>>(py, R_REL, D, KPAD,
        pahi + (size_t)N_ENT * KPAD, palo + (size_t)N_ENT * KPAD);
    cudaEventRecord(evRel, s1);
    cudaMemsetAsync(pcnt, 0, NT * sizeof(int), s1);
    hist_kernel<<<(E_EDGES + 255) / 256, 256, 0, s1>>>(edge_dst);
    scan1_kernel<<<NBLK, 256, 0, s1>>>();
    scan2_kernel<<<1, 256, 0, s1>>>(NBLK);
    scan3_kernel<<<NBLK, 256, 0, s1>>>();
    scatter_kernel<<<(E_EDGES + 255) / 256, 256, 0, s1>>>(edge_src, edge_dst, edge_w);
    cudaEventRecord(evCSR, s1);
    detect_mask_kernel<<<1, 256, 0, s1>>>((const unsigned char*)d_in[21]);
    for (int dir = 0; dir < 2; dir++) {
        conv_splitT_kv<<<(512 * KPAD + 255) / 256, 256, 0, s1>>>(
            Wk + (size_t)dir * D * HD, Wv + (size_t)dir * D * HD,
            pwkvhi + (size_t)dir * 512 * KPAD, pwkvlo + (size_t)dir * 512 * KPAD);
        conv_splitT<<<(HD * KPAD + 255) / 256, 256, 0, s1>>>(Wq + (size_t)dir * D * HD,
            D, HD, KPAD, pwqhi + (size_t)dir * HD * KPAD, pwqlo + (size_t)dir * HD * KPAD);
        // Wcomb_dir = Wo_dir [HD,300] @ Wprox_dir [300,300]  (fp32)
        sgemm_rr<<<dim3(3, 2), 256, 0, s1>>>(
            Wo + (size_t)dir * HD * D, D, Wprox + (size_t)dir * D * D, D,
            pwcomb + (size_t)dir * HD * D, D, HD, D, HD == 256 ? D : D, nullptr);
        conv_splitT_off<<<(D * HD + 255) / 256, 256, 0, s1>>>(
            pwcomb + (size_t)dir * HD * D, HD, D, 512, dir * HD, pwchi, pwclo);
    }
    cudaEventRecord(evW, s1);

    // ===== s0: main GCN chain =====
    conv_split4<<<(N_ENT * (KPAD / 4) + 255) / 256, 256, 0, s0>>>(e_x, N_ENT, D, KPAD, pahi, palo);
    conv_splitT<<<(D * KPAD + 255) / 256, 256, 0, s0>>>(W1, D, D, KPAD, pw1hi, pw1lo);
    conv_splitT<<<(D * KPAD + 255) / 256, 256, 0, s0>>>(W2, D, D, KPAD, pw2hi, pw2lo);
    cudaStreamWaitEvent(s0, evRel, 0);
    mma_gemm<<<dim3(3, MGRID), 256, SMEM, s0>>>(pahi, palo, pw1hi, pw1lo,
        py, nullptr, nullptr, NT, D, D, KPAD, nullptr);
    cudaStreamWaitEvent(s0, evCSR, 0);
    segsum_kernel<<<NT / 8, 256, 0, s0>>>(py, nullptr, pahi, palo, b1, 1);
    mma_gemm<<<dim3(3, MGRID), 256, SMEM, s0>>>(pahi, palo, pw2hi, pw2lo,
        py, nullptr, nullptr, NT, D, D, KPAD, nullptr);
    segsum_kernel<<<NT / 8, 256, 0, s0>>>(py, px, pahi, palo, b2, 0);
    cudaEventRecord(evH2, s0);

    // ===== s1: gather anchors + Q GEMM (overlaps Ekv on s0) =====
    cudaStreamWaitEvent(s1, evH2, 0);
    gather_ker2_kernel<<<2 * B, 320, 0, s1>>>((const int*)d_in[17], (const int*)d_in[18], out + 1);
    mma_gemm<<<dim3(4, 2 * B / 128), 256, SMEM, s1>>>(pkhi, pklo, pwqhi, pwqlo,
        pq, nullptr, nullptr, 2 * B, 512, 512, KPAD, nullptr);

    // ===== s0: Ekv per dir (pipelined with attention on s1) =====
    cudaStreamWaitEvent(s0, evW, 0);
    mma_gemm<<<dim3(4, MGRID), 256, SMEM, s0>>>(pahi, palo, pwkvhi, pwkvlo,
        pekv, nullptr, nullptr, NT, 512, 1024, KPAD, nullptr);
    cudaEventRecord(evE0, s0);
    mma_gemm<<<dim3(4, MGRID), 256, SMEM, s0>>>(pahi, palo,
        pwkvhi + (size_t)512 * KPAD, pwkvlo + (size_t)512 * KPAD,
        pekv + 512, nullptr, nullptr, NT, 512, 1024, KPAD, nullptr);
    cudaEventRecord(evE1, s0);

    // ===== s1: attention per dir (dir0 overlaps Ekv dir1) =====
    cudaStreamWaitEvent(s1, evE0, 0);
    attn_dir<<<2 * B * H / 8, 256, 0, s1>>>(0,
        (const int*)d_in[20], (const int*)d_in[19], d_in[21],
        (const int*)d_in[26], (const int*)d_in[25], d_in[27]);
    cudaStreamWaitEvent(s1, evE1, 0);
    attn_dir<<<2 * B * H / 8, 256, 0, s1>>>(1,
        (const int*)d_in[23], (const int*)d_in[22], d_in[24],
        (const int*)d_in[29], (const int*)d_in[28], d_in[30]);
    cudaEventRecord(evAttn, s1);

    // ===== s0: fused prox = maskedCtx @ Wcomb + bprox, then norm/sim =====
    cudaStreamWaitEvent(s0, evAttn, 0);
    mma_gemm<<<dim3(3, 2 * B / 128), 256, SMEM, s0>>>(pchi, pclo, pwchi, pwclo,
        out + 1 + D, nullptr, nullptr, 2 * B, D, 2 * D, 512, bprox);
    norm2_kernel<<<2 * B / 8, 256, 0, s0>>>(out + 1);
    cudaMemsetAsync(pacc, 0, 2 * sizeof(float), s0);
    mma_sim<<<dim3(16, 16), 256, SMEM, s0>>>(pn1hi, pn1lo, pn2hi, pn2lo);
    finalize_kernel<<<1, 1, 0, s0>>>(out);
}

// round 16
// speedup vs baseline: 1.4814x; 1.4814x over previous
#include <cuda_runtime.h>
#include <cuda_bf16.h>
#include <cstdint>
#include <math.h>

#define N_ENT 50000
#define R_REL 400
#define D 300
#define NT 50400
#define E_EDGES 800000
#define B 2048
#define L 32
#define H 8
#define DK 32
#define HD 256
#define G1 0.9f
#define G2 0.2f
#define KPAD 320
#define KP6 608

// ---------------- device scratch ----------------
__device__ __align__(16) float g_x[NT * D];
__device__ __align__(16) float g_y[NT * D];
__device__ __align__(16) float g_ekv[(size_t)NT * 1024];       // [row][dir*512 + (K | V)]
__device__ __align__(16) float g_q[(size_t)2 * B * 512];       // [b2][dir*256 + hd]
__device__ __align__(16) float g_wcomb[2 * HD * D];            // Wo@Wp per dir, fp32
__device__ __align__(16) __nv_bfloat16 g_ahi[(size_t)NT * KPAD];
__device__ __align__(16) __nv_bfloat16 g_alo[(size_t)NT * KPAD];
__device__ __align__(16) __nv_bfloat16 g_w1hi[300 * KPAD];
__device__ __align__(16) __nv_bfloat16 g_w1lo[300 * KPAD];
__device__ __align__(16) __nv_bfloat16 g_w2hi[300 * KPAD];
__device__ __align__(16) __nv_bfloat16 g_w2lo[300 * KPAD];
__device__ __align__(16) __nv_bfloat16 g_wkvhi[1024 * KPAD];
__device__ __align__(16) __nv_bfloat16 g_wkvlo[1024 * KPAD];
__device__ __align__(16) __nv_bfloat16 g_wqhi[512 * KPAD];
__device__ __align__(16) __nv_bfloat16 g_wqlo[512 * KPAD];
__device__ __align__(16) __nv_bfloat16 g_wchi[300 * 512];      // Wcomb^T split (both dirs)
__device__ __align__(16) __nv_bfloat16 g_wclo[300 * 512];
__device__ __align__(16) __nv_bfloat16 g_khi[2 * B * KPAD];
__device__ __align__(16) __nv_bfloat16 g_klo[2 * B * KPAD];
__device__ __align__(16) __nv_bfloat16 g_chi[(size_t)2 * B * 512];  // masked ctx [b2][dir*256+hd]
__device__ __align__(16) __nv_bfloat16 g_clo[(size_t)2 * B * 512];
__device__ __align__(16) __nv_bfloat16 g_n1hi[B * KP6];
__device__ __align__(16) __nv_bfloat16 g_n1lo[B * KP6];
__device__ __align__(16) __nv_bfloat16 g_n2hi[B * KP6];
__device__ __align__(16) __nv_bfloat16 g_n2lo[B * KP6];
__device__ int   g_cnt[NT];
__device__ int   g_cursor[NT];
__device__ int   g_rowptr[NT + 1];
__device__ int   g_bsum[256];
__device__ int   g_csr_src[E_EDGES];
__device__ float g_csr_w[E_EDGES];
__device__ float g_acc[2];
__device__ int   g_maskmode;

// ---------------- PTX helpers ----------------
__device__ __forceinline__ uint32_t smem_u32(const void* p) {
    uint32_t a;
    asm("{ .reg .u64 t; cvta.to.shared.u64 t, %1; cvt.u32.u64 %0, t; }" : "=r"(a) : "l"(p));
    return a;
}
__device__ __forceinline__ void cpa16(uint32_t s, const void* g) {
    asm volatile("cp.async.cg.shared.global [%0], [%1], 16;" :: "r"(s), "l"(g));
}
__device__ __forceinline__ void cpa_commit() { asm volatile("cp.async.commit_group;" ::); }
template <int NN> __device__ __forceinline__ void cpa_wait() {
    asm volatile("cp.async.wait_group %0;" :: "n"(NN));
}
__device__ __forceinline__ void ldm4(uint32_t* r, uint32_t a) {
    asm volatile("ldmatrix.sync.aligned.m8n8.x4.shared.b16 {%0,%1,%2,%3}, [%4];"
        : "=r"(r[0]), "=r"(r[1]), "=r"(r[2]), "=r"(r[3]) : "r"(a));
}
__device__ __forceinline__ void mma16816(float* c, const uint32_t* a, const uint32_t* b) {
    asm volatile("mma.sync.aligned.m16n8k16.row.col.f32.bf16.bf16.f32 "
        "{%0,%1,%2,%3}, {%4,%5,%6,%7}, {%8,%9}, {%0,%1,%2,%3};"
        : "+f"(c[0]), "+f"(c[1]), "+f"(c[2]), "+f"(c[3])
        : "r"(a[0]), "r"(a[1]), "r"(a[2]), "r"(a[3]), "r"(b[0]), "r"(b[1]));
}

// ---------------- mask dtype autodetect ----------------
__device__ __forceinline__ int read_mask(const void* p, int i) {
    if (g_maskmode) return ((const unsigned char*)p)[i] != 0;
    return ((const int*)p)[i] != 0;
}
__global__ void detect_mask_kernel(const unsigned char* __restrict__ m) {
    __shared__ int found;
    if (threadIdx.x == 0) found = 0;
    __syncthreads();
    for (int i = threadIdx.x; i < 4096; i += 256)
        if ((i & 3) && m[i]) found = 1;
    __syncthreads();
    if (threadIdx.x == 0) g_maskmode = found;
}

// ---------------- conversions ----------------
__global__ void conv_split(const float* __restrict__ src, int rows, int scols, int kpad,
                           __nv_bfloat16* __restrict__ hi, __nv_bfloat16* __restrict__ lo) {
    int idx = blockIdx.x * blockDim.x + threadIdx.x;
    if (idx >= rows * kpad) return;
    int r = idx / kpad, c = idx - r * kpad;
    float v = (c < scols) ? src[(size_t)r * scols + c] : 0.f;
    __nv_bfloat16 h = __float2bfloat16(v);
    hi[idx] = h;
    lo[idx] = __float2bfloat16(v - __bfloat162float(h));
}
__global__ void conv_split4(const float* __restrict__ src, int rows, int scols, int kpad,
                            __nv_bfloat16* __restrict__ hi, __nv_bfloat16* __restrict__ lo) {
    int idx = blockIdx.x * blockDim.x + threadIdx.x;
    int kq = kpad >> 2;
    if (idx >= rows * kq) return;
    int r = idx / kq, c4 = (idx - r * kq) << 2;
    float4 v = make_float4(0.f, 0.f, 0.f, 0.f);
    if (c4 + 4 <= scols)
        v = *reinterpret_cast<const float4*>(src + (size_t)r * scols + c4);
    __nv_bfloat16 h[4], l[4];
    float vf[4] = {v.x, v.y, v.z, v.w};
#pragma unroll
    for (int j = 0; j < 4; j++) {
        h[j] = __float2bfloat16(vf[j]);
        l[j] = __float2bfloat16(vf[j] - __bfloat162float(h[j]));
    }
    size_t off = (size_t)r * kpad + c4;
    *reinterpret_cast<uint2*>(hi + off) = *reinterpret_cast<uint2*>(h);
    *reinterpret_cast<uint2*>(lo + off) = *reinterpret_cast<uint2*>(l);
}
__global__ void conv_splitT(const float* __restrict__ W, int K, int Nn, int kpad,
                            __nv_bfloat16* __restrict__ hi, __nv_bfloat16* __restrict__ lo) {
    int idx = blockIdx.x * blockDim.x + threadIdx.x;
    if (idx >= Nn * kpad) return;
    int n = idx / kpad, k = idx - n * kpad;
    float v = (k < K) ? W[(size_t)k * Nn + n] : 0.f;
    __nv_bfloat16 h = __float2bfloat16(v);
    hi[idx] = h;
    lo[idx] = __float2bfloat16(v - __bfloat162float(h));
}
// writes only k in [0,K) at column offset koff (no padding writes)
__global__ void conv_splitT_off(const float* __restrict__ W, int K, int Nn, int kpad, int koff,
                                __nv_bfloat16* __restrict__ hi, __nv_bfloat16* __restrict__ lo) {
    int idx = blockIdx.x * blockDim.x + threadIdx.x;
    if (idx >= Nn * K) return;
    int n = idx / K, k = idx - n * K;
    float v = W[(size_t)k * Nn + n];
    __nv_bfloat16 h = __float2bfloat16(v);
    size_t o = (size_t)n * kpad + koff + k;
    hi[o] = h;
    lo[o] = __float2bfloat16(v - __bfloat162float(h));
}
__global__ void conv_splitT_kv(const float* __restrict__ Wk, const float* __restrict__ Wv,
                               __nv_bfloat16* __restrict__ hi, __nv_bfloat16* __restrict__ lo) {
    int idx = blockIdx.x * blockDim.x + threadIdx.x;
    if (idx >= 512 * KPAD) return;
    int n = idx / KPAD, k = idx - n * KPAD;
    float v = 0.f;
    if (k < D) v = (n < HD) ? Wk[(size_t)k * HD + n] : Wv[(size_t)k * HD + (n - HD)];
    __nv_bfloat16 h = __float2bfloat16(v);
    hi[idx] = h;
    lo[idx] = __float2bfloat16(v - __bfloat162float(h));
}

// =====================================================================
// bf16x3 warp-MMA GEMM core
// =====================================================================
__device__ __forceinline__ void mma_core(
    const __nv_bfloat16* __restrict__ Ahi, const __nv_bfloat16* __restrict__ Alo,
    const __nv_bfloat16* __restrict__ Bhi, const __nv_bfloat16* __restrict__ Blo,
    int M, int Ntot, int kpad, int m0, int n0g,
    uint32_t sbase, float acc[2][8][4])
{
    const int tid = threadIdx.x;
    const int lane = tid & 31;
    const int wid = tid >> 5;
    const int wm = (wid & 3) * 32;
    const int wn = (wid >> 2) * 64;
    const int NS2 = kpad >> 5;

    auto load_stage = [&](int slot, int ks) {
        int kb = ks << 5;
        uint32_t st = sbase + (uint32_t)slot * 32768u;
#pragma unroll
        for (int rep = 0; rep < 8; rep++) {
            int i = tid + rep * 256;
            int region = i >> 10;
            int il = i & 1023;
            int v = il >> 9, r = (il >> 2) & 127, c = il & 3;
            int pc = c ^ ((r >> 1) & 3);
            const __nv_bfloat16* src;
            if (region == 0) {
                int gr = m0 + r; if (gr >= M) gr = M - 1;
                src = (v ? Alo : Ahi) + (size_t)gr * kpad + kb + c * 8;
            } else {
                int gr = n0g + r; if (gr >= Ntot) gr = Ntot - 1;
                src = (v ? Blo : Bhi) + (size_t)gr * kpad + kb + c * 8;
            }
            cpa16(st + (uint32_t)region * 16384u + (uint32_t)v * 8192u
                  + (uint32_t)r * 64u + (uint32_t)pc * 16u, src);
        }
        cpa_commit();
    };

    load_stage(0, 0);
    load_stage(1, 1);

    const int a_r = wm + ((lane >> 3) & 1) * 8 + (lane & 7);
    const int a_c = lane >> 4;
    const int b_r = wn + ((lane >> 4) & 1) * 8 + (lane & 7);
    const int b_c = (lane >> 3) & 1;

    for (int i = 0; i < NS2; i++) {
        if (i + 1 < NS2) cpa_wait<1>(); else cpa_wait<0>();
        __syncthreads();
        if (i + 2 < NS2) load_stage((i + 2) % 3, i + 2);
        uint32_t st = sbase + (uint32_t)(i % 3) * 32768u;
#pragma unroll
        for (int hh = 0; hh < 2; hh++) {
            int cb = hh * 2;
            uint32_t af[2][2][4];
#pragma unroll
            for (int v = 0; v < 2; v++)
#pragma unroll
                for (int t = 0; t < 2; t++) {
                    int r2 = a_r + t * 16;
                    int pc = (cb + a_c) ^ ((r2 >> 1) & 3);
                    ldm4(af[v][t], st + (uint32_t)v * 8192u + (uint32_t)r2 * 64u
                                   + (uint32_t)pc * 16u);
                }
            uint32_t bf[2][8][2];
#pragma unroll
            for (int v = 0; v < 2; v++)
#pragma unroll
                for (int p = 0; p < 4; p++) {
                    int r2 = b_r + p * 16;
                    int pc = (cb + b_c) ^ ((r2 >> 1) & 3);
                    uint32_t tmp[4];
                    ldm4(tmp, st + 16384u + (uint32_t)v * 8192u + (uint32_t)r2 * 64u
                              + (uint32_t)pc * 16u);
                    bf[v][p * 2][0] = tmp[0]; bf[v][p * 2][1] = tmp[1];
                    bf[v][p * 2 + 1][0] = tmp[2]; bf[v][p * 2 + 1][1] = tmp[3];
                }
#pragma unroll
            for (int t = 0; t < 2; t++)
#pragma unroll
                for (int nt = 0; nt < 8; nt++) {
                    mma16816(acc[t][nt], af[0][t], bf[0][nt]);
                    mma16816(acc[t][nt], af[0][t], bf[1][nt]);
                    mma16816(acc[t][nt], af[1][t], bf[0][nt]);
                }
        }
    }
}

__global__ __launch_bounds__(256) void mma_gemm(
    const __nv_bfloat16* __restrict__ Ahi, const __nv_bfloat16* __restrict__ Alo,
    const __nv_bfloat16* __restrict__ Bhi, const __nv_bfloat16* __restrict__ Blo,
    float* __restrict__ C, __nv_bfloat16* __restrict__ Chi, __nv_bfloat16* __restrict__ Clo,
    int M, int Ntot, int ldc, int kpad,
    const float* __restrict__ bias)
{
    extern __shared__ char dsm[];
    const int lane = threadIdx.x & 31;
    const int wid = threadIdx.x >> 5;
    const int wm = (wid & 3) * 32, wn = (wid >> 2) * 64;
    const int m0 = blockIdx.y * 128, n0g = blockIdx.x * 128;
    float acc[2][8][4];
#pragma unroll
    for (int t = 0; t < 2; t++)
#pragma unroll
        for (int nt = 0; nt < 8; nt++)
#pragma unroll
            for (int j = 0; j < 4; j++) acc[t][nt][j] = 0.f;

    mma_core(Ahi, Alo, Bhi, Blo, M, Ntot, kpad, m0, n0g, smem_u32(dsm), acc);

#pragma unroll
    for (int t = 0; t < 2; t++) {
        int gm0 = m0 + wm + t * 16 + (lane >> 2);
#pragma unroll
        for (int nt = 0; nt < 8; nt++) {
            int gn = n0g + wn + nt * 8 + ((lane & 3) << 1);
            if (gn >= Ntot) continue;
#pragma unroll
            for (int half = 0; half < 2; half++) {
                int gm = gm0 + half * 8;
                if (gm >= M) continue;
                float c0 = acc[t][nt][half * 2 + 0];
                float c1 = acc[t][nt][half * 2 + 1];
                if (bias) { c0 += bias[gn]; c1 += bias[gn + 1]; }
                size_t orow = (size_t)gm * ldc;
                if (Chi) {
                    __nv_bfloat16 h0 = __float2bfloat16(c0);
                    Chi[orow + gn] = h0;
                    Clo[orow + gn] = __float2bfloat16(c0 - __bfloat162float(h0));
                    if (gn + 1 < Ntot) {
                        __nv_bfloat16 h1 = __float2bfloat16(c1);
                        Chi[orow + gn + 1] = h1;
                        Clo[orow + gn + 1] = __float2bfloat16(c1 - __bfloat162float(h1));
                    }
                } else {
                    C[orow + gn] = c0;
                    if (gn + 1 < Ntot) C[orow + gn + 1] = c1;
                }
            }
        }
    }
}

// sim = n1 * n2^T with in-register loss reduction
__global__ __launch_bounds__(256) void mma_sim(
    const __nv_bfloat16* __restrict__ Ahi, const __nv_bfloat16* __restrict__ Alo,
    const __nv_bfloat16* __restrict__ Bhi, const __nv_bfloat16* __restrict__ Blo)
{
    extern __shared__ char dsm[];
    const int tid = threadIdx.x;
    const int lane = tid & 31;
    const int wid = tid >> 5;
    const int wm = (wid & 3) * 32, wn = (wid >> 2) * 64;
    const int m0 = blockIdx.y * 128, n0g = blockIdx.x * 128;
    float acc[2][8][4];
#pragma unroll
    for (int t = 0; t < 2; t++)
#pragma unroll
        for (int nt = 0; nt < 8; nt++)
#pragma unroll
            for (int j = 0; j < 4; j++) acc[t][nt][j] = 0.f;

    mma_core(Ahi, Alo, Bhi, Blo, B, B, KP6, m0, n0g, smem_u32(dsm), acc);

    float neg = 0.f, dia = 0.f;
#pragma unroll
    for (int t = 0; t < 2; t++) {
        int gm0 = m0 + wm + t * 16 + (lane >> 2);
#pragma unroll
        for (int nt = 0; nt < 8; nt++) {
            int gn = n0g + wn + nt * 8 + ((lane & 3) << 1);
#pragma unroll
            for (int half = 0; half < 2; half++) {
                int gm = gm0 + half * 8;
#pragma unroll
                for (int j = 0; j < 2; j++) {
                    float c = acc[t][nt][half * 2 + j];
                    if (gm == gn + j) dia += fminf(c, G1);
                    else neg += fmaxf(c, G2);
                }
            }
        }
    }
    __syncthreads();
    float* red = (float*)dsm;
    red[tid] = neg; __syncthreads();
    for (int s2 = 128; s2; s2 >>= 1) { if (tid < s2) red[tid] += red[tid + s2]; __syncthreads(); }
    if (tid == 0) atomicAdd(&g_acc[0], red[0]);
    __syncthreads();
    red[tid] = dia; __syncthreads();
    for (int s2 = 128; s2; s2 >>= 1) { if (tid < s2) red[tid] += red[tid + s2]; __syncthreads(); }
    if (tid == 0) atomicAdd(&g_acc[1], red[0]);
}

// ---------------- SIMT SGEMM (tiny Wrel + Wcomb GEMMs) ----------------
__global__ __launch_bounds__(256) void sgemm_rr(
    const float* __restrict__ A, int lda, const float* __restrict__ Bm, int ldb,
    float* __restrict__ C, int ldc, int M, int Nn, int K,
    const float* __restrict__ bias)
{
    __shared__ float As[8][128];
    __shared__ float Bs[8][128];
    const int tid = threadIdx.x;
    const int m0 = blockIdx.y * 128, n0 = blockIdx.x * 128;
    const int arow = tid >> 1, acol = (tid & 1) << 2;
    const int brow = tid >> 5, bcol = (tid & 31) << 2;
    const int ty = tid >> 4, tx = tid & 15;
    const int tm = ty << 3, tn = tx << 3;
    float acc[8][8];
#pragma unroll
    for (int i = 0; i < 8; i++)
#pragma unroll
        for (int j = 0; j < 8; j++) acc[i][j] = 0.f;
    for (int k0 = 0; k0 < K; k0 += 8) {
        float4 av = make_float4(0.f, 0.f, 0.f, 0.f);
        { int gm = m0 + arow, gk = k0 + acol;
          if (gm < M && gk < K) av = *reinterpret_cast<const float4*>(A + (size_t)gm * lda + gk); }
        As[acol + 0][arow] = av.x; As[acol + 1][arow] = av.y;
        As[acol + 2][arow] = av.z; As[acol + 3][arow] = av.w;
        float4 bv = make_float4(0.f, 0.f, 0.f, 0.f);
        { int gk = k0 + brow, gn = n0 + bcol;
          if (gk < K && gn < Nn) bv = *reinterpret_cast<const float4*>(Bm + (size_t)gk * ldb + gn); }
        *reinterpret_cast<float4*>(&Bs[brow][bcol]) = bv;
        __syncthreads();
#pragma unroll
        for (int kk = 0; kk < 8; kk++) {
            float4 a0 = *reinterpret_cast<const float4*>(&As[kk][tm]);
            float4 a1 = *reinterpret_cast<const float4*>(&As[kk][tm + 4]);
            float4 b0 = *reinterpret_cast<const float4*>(&Bs[kk][tn]);
            float4 b1 = *reinterpret_cast<const float4*>(&Bs[kk][tn + 4]);
            float af[8] = {a0.x, a0.y, a0.z, a0.w, a1.x, a1.y, a1.z, a1.w};
            float bf[8] = {b0.x, b0.y, b0.z, b0.w, b1.x, b1.y, b1.z, b1.w};
#pragma unroll
            for (int i = 0; i < 8; i++)
#pragma unroll
                for (int j = 0; j < 8; j++) acc[i][j] = fmaf(af[i], bf[j], acc[i][j]);
        }
        __syncthreads();
    }
#pragma unroll
    for (int i = 0; i < 8; i++) {
        int gm = m0 + tm + i;
        if (gm >= M) continue;
#pragma unroll
        for (int j = 0; j < 8; j++) {
            int gn = n0 + tn + j;
            if (gn >= Nn) continue;
            float c = acc[i][j];
            if (bias) c += bias[gn];
            C[(size_t)gm * ldc + gn] = c;
        }
    }
}

// ---------------- CSR build ----------------
__global__ void hist_kernel(const int* __restrict__ dst) {
    int e = blockIdx.x * blockDim.x + threadIdx.x;
    if (e < E_EDGES) atomicAdd(&g_cnt[dst[e]], 1);
}
__global__ void scan1_kernel() {
    __shared__ int sh[256];
    int i = blockIdx.x * 256 + threadIdx.x;
    sh[threadIdx.x] = (i < NT) ? g_cnt[i] : 0;
    __syncthreads();
    for (int o = 128; o; o >>= 1) { if (threadIdx.x < o) sh[threadIdx.x] += sh[threadIdx.x + o]; __syncthreads(); }
    if (!threadIdx.x) g_bsum[blockIdx.x] = sh[0];
}
__global__ void scan2_kernel(int nb) {
    __shared__ int sh[256];
    int t = threadIdx.x;
    int v = (t < nb) ? g_bsum[t] : 0;
    sh[t] = v; __syncthreads();
    for (int o = 1; o < 256; o <<= 1) {
        int u = (t >= o) ? sh[t - o] : 0; __syncthreads();
        sh[t] += u; __syncthreads();
    }
    g_bsum[t] = sh[t] - v;
}
__global__ void scan3_kernel() {
    __shared__ int sh[256];
    int t = threadIdx.x, i = blockIdx.x * 256 + t;
    int v = (i < NT) ? g_cnt[i] : 0;
    sh[t] = v; __syncthreads();
    for (int o = 1; o < 256; o <<= 1) {
        int u = (t >= o) ? sh[t - o] : 0; __syncthreads();
        sh[t] += u; __syncthreads();
    }
    int off = g_bsum[blockIdx.x] + sh[t] - v;
    if (i < NT) {
        g_rowptr[i] = off; g_cursor[i] = off;
        if (i == NT - 1) g_rowptr[NT] = off + v;
    }
}
__global__ void scatter_kernel(const int* __restrict__ src, const int* __restrict__ dst,
                               const float* __restrict__ w) {
    int e = blockIdx.x * blockDim.x + threadIdx.x;
    if (e < E_EDGES) {
        int d = dst[e];
        int p = atomicAdd(&g_cursor[d], 1);
        g_csr_src[p] = src[e];
        g_csr_w[p] = w[e];
    }
}

// ---------------- segment sum (float4, fused bias/relu + dual output) ----
__global__ void segsum_kernel(const float* __restrict__ Y, float* __restrict__ O,
                              __nv_bfloat16* __restrict__ Ohi, __nv_bfloat16* __restrict__ Olo,
                              const float* __restrict__ bias, int doRelu) {
    int gw = (blockIdx.x * blockDim.x + threadIdx.x) >> 5;
    int lane = threadIdx.x & 31;
    if (gw >= NT) return;
    int beg = g_rowptr[gw], end = g_rowptr[gw + 1];
    float4 acc[3];
#pragma unroll
    for (int j = 0; j < 3; j++) acc[j] = make_float4(0.f, 0.f, 0.f, 0.f);
    const int v2 = (lane < 11);
    for (int e = beg; e < end; e++) {
        int sI = g_csr_src[e];
        float w = g_csr_w[e];
        const float4* yr = reinterpret_cast<const float4*>(Y + (size_t)sI * D);
#pragma unroll
        for (int j = 0; j < 3; j++) {
            if (j < 2 || v2) {
                float4 v = yr[lane + (j << 5)];
                acc[j].x = fmaf(w, v.x, acc[j].x);
                acc[j].y = fmaf(w, v.y, acc[j].y);
                acc[j].z = fmaf(w, v.z, acc[j].z);
                acc[j].w = fmaf(w, v.w, acc[j].w);
            }
        }
    }
    const float4* b4 = reinterpret_cast<const float4*>(bias);
#pragma unroll
    for (int j = 0; j < 3; j++) {
        if (j == 2 && !v2) continue;
        int c4 = lane + (j << 5);
        float4 bb = b4[c4];
        float4 v = acc[j];
        v.x += bb.x; v.y += bb.y; v.z += bb.z; v.w += bb.w;
        if (doRelu) {
            v.x = fmaxf(v.x, 0.f); v.y = fmaxf(v.y, 0.f);
            v.z = fmaxf(v.z, 0.f); v.w = fmaxf(v.w, 0.f);
        }
        if (O) reinterpret_cast<float4*>(O + (size_t)gw * D)[c4] = v;
        if (Ohi) {
            __nv_bfloat16 h[4], l[4];
            float vf[4] = {v.x, v.y, v.z, v.w};
#pragma unroll
            for (int q = 0; q < 4; q++) {
                h[q] = __float2bfloat16(vf[q]);
                l[q] = __float2bfloat16(vf[q] - __bfloat162float(h[q]));
            }
            size_t off = (size_t)gw * KPAD + c4 * 4;
            *reinterpret_cast<uint2*>(Ohi + off) = *reinterpret_cast<uint2*>(h);
            *reinterpret_cast<uint2*>(Olo + off) = *reinterpret_cast<uint2*>(l);
        }
    }
}

// ---------------- encoder pieces ----------------
__global__ void gather_ker2_kernel(const int* __restrict__ ids_l, const int* __restrict__ ids_r,
                                   float* __restrict__ outbase) {
    int b2 = blockIdx.x, c = threadIdx.x;
    if (c >= D) return;
    int side = (b2 >= B);
    int b = b2 - side * B;
    const int* ids = side ? ids_r : ids_l;
    float v = g_x[(size_t)ids[b] * D + c];
    outbase[(size_t)b2 * (2 * D) + c] = v;
    __nv_bfloat16 h = __float2bfloat16(v);
    g_khi[(size_t)b2 * KPAD + c] = h;
    g_klo[(size_t)b2 * KPAD + c] = __float2bfloat16(v - __bfloat162float(h));
}

// attention: all (dir, side) in ONE launch; writes MASK-SCALED ctx to [b2][dir*256+hd]
__global__ __launch_bounds__(256) void attn_fused(
    const int* __restrict__ h00, const int* __restrict__ r00, const void* __restrict__ m00,
    const int* __restrict__ h01, const int* __restrict__ r01, const void* __restrict__ m01,
    const int* __restrict__ h10, const int* __restrict__ r10, const void* __restrict__ m10,
    const int* __restrict__ h11, const int* __restrict__ r11, const void* __restrict__ m11)
{
    __shared__ float T[8][32][33];
    int wid = threadIdx.x >> 5, lane = threadIdx.x & 31;
    int gw = blockIdx.x * 8 + wid;
    int h = gw & 7;
    int d2 = gw >> 3;                 // dir*4096 + b2
    int dir = d2 >> 12;
    int b2 = d2 & 4095;
    int side = b2 >> 11;
    int b = b2 & 2047;
    const int* head; const int* rel; const void* mask;
    if (dir == 0) { if (side == 0) { head = h00; rel = r00; mask = m00; }
                    else           { head = h01; rel = r01; mask = m01; } }
    else          { if (side == 0) { head = h10; rel = r10; mask = m10; }
                    else           { head = h11; rel = r11; mask = m11; } }
    int h32 = h * 32;
    int kcol = dir * 512 + h32;
    int t_l = head[b * L + lane];
    int r_l = N_ENT + rel[b * L + lane];
    float (*Tl)[33] = T[wid];
#pragma unroll 4
    for (int l = 0; l < 32; l++) {
        int t = __shfl_sync(0xffffffffu, t_l, l);
        int r = __shfl_sync(0xffffffffu, r_l, l);
        Tl[l][lane] = g_ekv[(size_t)t * 1024 + kcol + lane]
                    + g_ekv[(size_t)r * 1024 + kcol + lane];
    }
    float qv = g_q[(size_t)b2 * 512 + dir * 256 + h32 + lane];
    __syncwarp();
    float s = 0.f;
#pragma unroll
    for (int d = 0; d < 32; d++)
        s = fmaf(__shfl_sync(0xffffffffu, qv, d), Tl[lane][d], s);
    int mk = read_mask(mask, b * L + lane);
    unsigned bal = __ballot_sync(0xffffffffu, mk);
    s = mk ? s * 0.17677669529663687f : -1e9f;
    float mx = s;
#pragma unroll
    for (int o = 16; o; o >>= 1) mx = fmaxf(mx, __shfl_xor_sync(0xffffffffu, mx, o));
    float e = expf(s - mx);
    float sum = e;
#pragma unroll
    for (int o = 16; o; o >>= 1) sum += __shfl_xor_sync(0xffffffffu, sum, o);
    float at = e / sum;
    float c = 0.f;
#pragma unroll 4
    for (int l = 0; l < 32; l++) {
        int t = __shfl_sync(0xffffffffu, t_l, l);
        int r = __shfl_sync(0xffffffffu, r_l, l);
        float v = g_ekv[(size_t)t * 1024 + kcol + 256 + lane]
                + g_ekv[(size_t)r * 1024 + kcol + 256 + lane];
        c = fmaf(__shfl_sync(0xffffffffu, at, l), v, c);
    }
    if (bal == 0u) c = 0.f;           // mask.any row-zero folded into ctx
    __nv_bfloat16 hc = __float2bfloat16(c);
    size_t oidx = (size_t)b2 * 512 + dir * 256 + h32 + lane;
    g_chi[oidx] = hc;
    g_clo[oidx] = __float2bfloat16(c - __bfloat162float(hc));
}

// ---------------- cosine norm over 2B rows ----------------
__global__ void norm2_kernel(const float* __restrict__ srcbase) {
    int w2 = (blockIdx.x * blockDim.x + threadIdx.x) >> 5;
    int lane = threadIdx.x & 31;
    if (w2 >= 2 * B) return;
    const float* s = srcbase + (size_t)w2 * (2 * D);
    float ss = 0.f;
    for (int c = lane; c < 2 * D; c += 32) { float v = s[c]; ss = fmaf(v, v, ss); }
#pragma unroll
    for (int o = 16; o; o >>= 1) ss += __shfl_xor_sync(0xffffffffu, ss, o);
    float sc = 1.f / fmaxf(sqrtf(ss), 1e-8f);
    int side = (w2 >= B);
    int w = w2 - side * B;
    __nv_bfloat16* dhi = side ? g_n2hi : g_n1hi;
    __nv_bfloat16* dlo = side ? g_n2lo : g_n1lo;
    for (int c = lane; c < 2 * D; c += 32) {
        float v = s[c] * sc;
        __nv_bfloat16 h = __float2bfloat16(v);
        dhi[(size_t)w * KP6 + c] = h;
        dlo[(size_t)w * KP6 + c] = __float2bfloat16(v - __bfloat162float(h));
    }
}
__global__ void finalize_kernel(float* __restrict__ out) {
    float neg_sum = g_acc[0] + (float)B * fmaxf(0.f, G2);
    float neg_part = neg_sum / (float)((size_t)B * B);
    float pos_part = g_acc[1] / (float)B;
    out[0] = neg_part - G2 - pos_part + G1;
}

// =====================================================================
extern "C" void kernel_launch(void* const* d_in, const int* in_sizes, int n_in,
                              void* d_out, int out_size) {
    const float* e_x    = (const float*)d_in[0];
    const float* r_x    = (const float*)d_in[1];
    const float* edge_w = (const float*)d_in[2];
    const float* Wrel   = (const float*)d_in[3];
    const float* brel   = (const float*)d_in[4];
    const float* W1     = (const float*)d_in[5];
    const float* b1     = (const float*)d_in[6];
    const float* W2     = (const float*)d_in[7];
    const float* b2     = (const float*)d_in[8];
    const float* Wprox  = (const float*)d_in[9];
    const float* bprox  = (const float*)d_in[10];
    const float* Wq     = (const float*)d_in[11];
    const float* Wk     = (const float*)d_in[12];
    const float* Wv     = (const float*)d_in[13];
    const float* Wo     = (const float*)d_in[14];
    const int* edge_src = (const int*)d_in[15];
    const int* edge_dst = (const int*)d_in[16];
    float* out = (float*)d_out;

    float *px, *py, *pekv, *pq, *pacc, *pwcomb;
    __nv_bfloat16 *pahi, *palo;
    __nv_bfloat16 *pw1hi, *pw1lo, *pw2hi, *pw2lo, *pwkvhi, *pwkvlo;
    __nv_bfloat16 *pwqhi, *pwqlo, *pwchi, *pwclo;
    __nv_bfloat16 *pkhi, *pklo, *pchi, *pclo;
    __nv_bfloat16 *pn1hi, *pn1lo, *pn2hi, *pn2lo;
    int *pcnt;
    cudaGetSymbolAddress((void**)&px, g_x);
    cudaGetSymbolAddress((void**)&py, g_y);
    cudaGetSymbolAddress((void**)&pekv, g_ekv);
    cudaGetSymbolAddress((void**)&pq, g_q);
    cudaGetSymbolAddress((void**)&pacc, g_acc);
    cudaGetSymbolAddress((void**)&pwcomb, g_wcomb);
    cudaGetSymbolAddress((void**)&pcnt, g_cnt);
    cudaGetSymbolAddress((void**)&pahi, g_ahi);
    cudaGetSymbolAddress((void**)&palo, g_alo);
    cudaGetSymbolAddress((void**)&pw1hi, g_w1hi);
    cudaGetSymbolAddress((void**)&pw1lo, g_w1lo);
    cudaGetSymbolAddress((void**)&pw2hi, g_w2hi);
    cudaGetSymbolAddress((void**)&pw2lo, g_w2lo);
    cudaGetSymbolAddress((void**)&pwkvhi, g_wkvhi);
    cudaGetSymbolAddress((void**)&pwkvlo, g_wkvlo);
    cudaGetSymbolAddress((void**)&pwqhi, g_wqhi);
    cudaGetSymbolAddress((void**)&pwqlo, g_wqlo);
    cudaGetSymbolAddress((void**)&pwchi, g_wchi);
    cudaGetSymbolAddress((void**)&pwclo, g_wclo);
    cudaGetSymbolAddress((void**)&pkhi, g_khi);
    cudaGetSymbolAddress((void**)&pklo, g_klo);
    cudaGetSymbolAddress((void**)&pchi, g_chi);
    cudaGetSymbolAddress((void**)&pclo, g_clo);
    cudaGetSymbolAddress((void**)&pn1hi, g_n1hi);
    cudaGetSymbolAddress((void**)&pn1lo, g_n1lo);
    cudaGetSymbolAddress((void**)&pn2hi, g_n2hi);
    cudaGetSymbolAddress((void**)&pn2lo, g_n2lo);

    cudaFuncSetAttribute(mma_gemm, cudaFuncAttributeMaxDynamicSharedMemorySize, 98304);
    cudaFuncSetAttribute(mma_sim, cudaFuncAttributeMaxDynamicSharedMemorySize, 98304);
    const int SMEM = 98304;
    const int NBLK = (NT + 255) / 256;
    const int MGRID = (NT + 127) / 128;

    static cudaStream_t s1 = nullptr;
    static cudaEvent_t evFork, evRel, evCSR, evW, evH2, evQ;
    if (!s1) {
        cudaStreamCreateWithFlags(&s1, cudaStreamNonBlocking);
        cudaEventCreateWithFlags(&evFork, cudaEventDisableTiming);
        cudaEventCreateWithFlags(&evRel,  cudaEventDisableTiming);
        cudaEventCreateWithFlags(&evCSR,  cudaEventDisableTiming);
        cudaEventCreateWithFlags(&evW,    cudaEventDisableTiming);
        cudaEventCreateWithFlags(&evH2,   cudaEventDisableTiming);
        cudaEventCreateWithFlags(&evQ,    cudaEventDisableTiming);
    }
    cudaStream_t s0 = 0;

    cudaEventRecord(evFork, s0);
    cudaStreamWaitEvent(s1, evFork, 0);

    // ===== s1: rel rows, CSR, mask detect, weight conversions, Wcomb =====
    sgemm_rr<<<dim3(3, 4), 256, 0, s1>>>(r_x, 2 * D, Wrel, D, py, D, R_REL, D, 2 * D, brel);
    conv_split<<<(R_REL * KPAD + 255) / 256, 256, 0, s1>>>(py, R_REL, D, KPAD,
        pahi + (size_t)N_ENT * KPAD, palo + (size_t)N_ENT * KPAD);
    cudaEventRecord(evRel, s1);
    cudaMemsetAsync(pcnt, 0, NT * sizeof(int), s1);
    hist_kernel<<<(E_EDGES + 255) / 256, 256, 0, s1>>>(edge_dst);
    scan1_kernel<<<NBLK, 256, 0, s1>>>();
    scan2_kernel<<<1, 256, 0, s1>>>(NBLK);
    scan3_kernel<<<NBLK, 256, 0, s1>>>();
    scatter_kernel<<<(E_EDGES + 255) / 256, 256, 0, s1>>>(edge_src, edge_dst, edge_w);
    cudaEventRecord(evCSR, s1);
    detect_mask_kernel<<<1, 256, 0, s1>>>((const unsigned char*)d_in[21]);
    for (int dir = 0; dir < 2; dir++) {
        conv_splitT_kv<<<(512 * KPAD + 255) / 256, 256, 0, s1>>>(
            Wk + (size_t)dir * D * HD, Wv + (size_t)dir * D * HD,
            pwkvhi + (size_t)dir * 512 * KPAD, pwkvlo + (size_t)dir * 512 * KPAD);
        conv_splitT<<<(HD * KPAD + 255) / 256, 256, 0, s1>>>(Wq + (size_t)dir * D * HD,
            D, HD, KPAD, pwqhi + (size_t)dir * HD * KPAD, pwqlo + (size_t)dir * HD * KPAD);
        // Wcomb_dir = Wo_dir [HD,300] @ Wprox rows [dir*300 .. dir*300+299]  (fp32)
        sgemm_rr<<<dim3(3, 2), 256, 0, s1>>>(
            Wo + (size_t)dir * HD * D, D, Wprox + (size_t)dir * D * D, D,
            pwcomb + (size_t)dir * HD * D, D, HD, D, D, nullptr);
        conv_splitT_off<<<(D * HD + 255) / 256, 256, 0, s1>>>(
            pwcomb + (size_t)dir * HD * D, HD, D, 512, dir * HD, pwchi, pwclo);
    }
    cudaEventRecord(evW, s1);

    // ===== s0: main GCN chain =====
    conv_split4<<<(N_ENT * (KPAD / 4) + 255) / 256, 256, 0, s0>>>(e_x, N_ENT, D, KPAD, pahi, palo);
    conv_splitT<<<(D * KPAD + 255) / 256, 256, 0, s0>>>(W1, D, D, KPAD, pw1hi, pw1lo);
    conv_splitT<<<(D * KPAD + 255) / 256, 256, 0, s0>>>(W2, D, D, KPAD, pw2hi, pw2lo);
    cudaStreamWaitEvent(s0, evRel, 0);
    mma_gemm<<<dim3(3, MGRID), 256, SMEM, s0>>>(pahi, palo, pw1hi, pw1lo,
        py, nullptr, nullptr, NT, D, D, KPAD, nullptr);
    cudaStreamWaitEvent(s0, evCSR, 0);
    segsum_kernel<<<NT / 8, 256, 0, s0>>>(py, nullptr, pahi, palo, b1, 1);
    mma_gemm<<<dim3(3, MGRID), 256, SMEM, s0>>>(pahi, palo, pw2hi, pw2lo,
        py, nullptr, nullptr, NT, D, D, KPAD, nullptr);
    segsum_kernel<<<NT / 8, 256, 0, s0>>>(py, px, pahi, palo, b2, 0);
    cudaEventRecord(evH2, s0);

    // ===== s1: gather anchors + Q GEMM (overlaps Ekv on s0) =====
    cudaStreamWaitEvent(s1, evH2, 0);
    gather_ker2_kernel<<<2 * B, 320, 0, s1>>>((const int*)d_in[17], (const int*)d_in[18], out + 1);
    mma_gemm<<<dim3(4, 2 * B / 128), 256, SMEM, s1>>>(pkhi, pklo, pwqhi, pwqlo,
        pq, nullptr, nullptr, 2 * B, 512, 512, KPAD, nullptr);
    cudaEventRecord(evQ, s1);

    // ===== s0: Ekv (both dirs, ONE GEMM — no overlap with attention) =====
    cudaStreamWaitEvent(s0, evW, 0);
    mma_gemm<<<dim3(8, MGRID), 256, SMEM, s0>>>(pahi, palo, pwkvhi, pwkvlo,
        pekv, nullptr, nullptr, NT, 1024, 1024, KPAD, nullptr);
    cudaStreamWaitEvent(s0, evQ, 0);
    attn_fused<<<2 * 2 * B * H / 8, 256, 0, s0>>>(
        (const int*)d_in[20], (const int*)d_in[19], d_in[21],
        (const int*)d_in[26], (const int*)d_in[25], d_in[27],
        (const int*)d_in[23], (const int*)d_in[22], d_in[24],
        (const int*)d_in[29], (const int*)d_in[28], d_in[30]);

    // ===== s0: fused prox = maskedCtx @ Wcomb + bprox, then norm/sim =====
    mma_gemm<<<dim3(3, 2 * B / 128), 256, SMEM, s0>>>(pchi, pclo, pwchi, pwclo,
        out + 1 + D, nullptr, nullptr, 2 * B, D, 2 * D, 512, bprox);
    norm2_kernel<<<2 * B / 8, 256, 0, s0>>>(out + 1);
    cudaMemsetAsync(pacc, 0, 2 * sizeof(float), s0);
    mma_sim<<<dim3(16, 16), 256, SMEM, s0>>>(pn1hi, pn1lo, pn2hi, pn2lo);
    finalize_kernel<<<1, 1, 0, s0>>>(out);
}